// round 17
// baseline (speedup 1.0000x reference)
#include <cuda_runtime.h>
#include <cstdint>
#include <cstring>

// Problem dims
#define BDIM 64
#define TDIM 512
#define KDIM 1024   // IN_DIM
#define HDIM 1024   // HID
#define MTOT (BDIM * TDIM)   // 32768 rows of the GEMM

// exp(-1/20) rounded to nearest fp32
#define ALPHA 0.9512294245007140f

// Scratch for I = x @ W^T + b   (128 MB, static device allocation — guard-safe)
__device__ float g_I[(size_t)MTOT * HDIM];

// Per-batch readiness counters (32 GEMM CTAs per batch). Zeroed each call.
__device__ unsigned int g_ready[BDIM];

typedef unsigned long long u64;

// packed fma: both lanes round exactly like scalar fma.rn.f32
__device__ __forceinline__ void fma2(u64& d, u64 a, u64 b) {
    asm("fma.rn.f32x2 %0, %1, %2, %0;" : "+l"(d) : "l"(a), "l"(b));
}
__device__ __forceinline__ u64 pack2(float lo, float hi) {
    u64 r;
    asm("mov.b64 %0, {%1, %2};" : "=l"(r) : "f"(lo), "f"(hi));
    return r;
}

// ---------------------------------------------------------------------------
// SGEMM (NT), Eigen-ordered accumulation (numerics VERIFIED R7/R9-R16):
//   per output: in-order FMA chain k ascending, fold (fadd) at k=1016,
//   fadd of 8-wide tail chain, fadd bias.
// v7 MIXED-PIPE PROBE: per thread per k-step, 24 FFMA2 (cols pairs p=0..2)
// + 16 scalar FFMA (cols colHi+2,3). If FFMA2's rt3 is a bank-SPACING
// constraint (fma pipe accepts 1 instr / 2 cyc), the scalars slot into the
// gaps: 80 instrs x 2 = 160 cyc/k-step/SMSP (vs 192). If FFMA2 BLOCKS issue
// for 3 cyc, this regresses to 208 — closing the question either way.
// Each output's k-chain order is unchanged -> bitwise-identical result.
// ---------------------------------------------------------------------------
constexpr int BM = 128, BN = 128, BK = 8, TM = 8, TN = 8;
constexpr int NKB = KDIM / BK;       // 128 tiles; tiles 0..126 = k<1016

__global__ __launch_bounds__(256, 1) void sgemm_nt_bias_eigen_f32x2(
    const float* __restrict__ A,      // [MTOT, KDIM] row-major
    const float* __restrict__ W,      // [HDIM, KDIM] row-major
    const float* __restrict__ bias)   // [HDIM]
{
    __shared__ float As[2][BK][BM];   // As[buf][k][m]
    __shared__ float Bs[2][BK][BN];   // Bs[buf][k][n]

    const int cRow = blockIdx.y;
    const int cCol = blockIdx.x;
    const int tid  = threadIdx.x;

    const int threadRow = (tid / 16) * TM;   // 0..120 (warp-broadcast A)
    const int colLo     = (tid % 16) * 4;    // cols colLo..colLo+3
    const int colHi     = colLo + 64;        // cols colHi..colHi+3

    // staging: one float4 per matrix per thread per k-tile
    const int innerRow = tid / 2;          // 0..127 (m or n index)
    const int innerCol = (tid % 2) * 4;    // k offset 0 or 4

    const float* Aptr = A + (size_t)cRow * BM * KDIM + (size_t)innerRow * KDIM + innerCol;
    const float* Wptr = W + (size_t)cCol * BN * KDIM + (size_t)innerRow * KDIM + innerCol;

    u64   acc2[TM * 3];    // packed pairs: cols (colLo,+1),(colLo+2,+3),(colHi,+1)
    float accS[TM * 2];    // scalar cols colHi+2, colHi+3
    #pragma unroll
    for (int i = 0; i < TM * 3; i++) acc2[i] = 0ull;
    #pragma unroll
    for (int i = 0; i < TM * 2; i++) accS[i] = 0.0f;

    // ---- stage tile 0 ----
    float4 ra = *reinterpret_cast<const float4*>(Aptr);
    float4 rb = *reinterpret_cast<const float4*>(Wptr);
    {
        const float av[4] = {ra.x, ra.y, ra.z, ra.w};
        const float bv[4] = {rb.x, rb.y, rb.z, rb.w};
        #pragma unroll
        for (int j = 0; j < 4; j++) {
            As[0][innerCol + j][innerRow] = av[j];
            Bs[0][innerCol + j][innerRow] = bv[j];
        }
    }
    __syncthreads();

    // ---- compute one k-tile from buffer `buf` (k ascending) ----
    auto compute_tile = [&](int buf) {
        #pragma unroll
        for (int k = 0; k < BK; k++) {
            float4 a0 = *reinterpret_cast<const float4*>(&As[buf][k][threadRow + 0]);
            float4 a1 = *reinterpret_cast<const float4*>(&As[buf][k][threadRow + 4]);
            float4 b0 = *reinterpret_cast<const float4*>(&Bs[buf][k][colLo]);  // conflict-free
            float4 b1 = *reinterpret_cast<const float4*>(&Bs[buf][k][colHi]);

            u64 n[3];
            memcpy(&n[0], &b0.x, 8); memcpy(&n[1], &b0.z, 8);
            memcpy(&n[2], &b1.x, 8);
            const float bs0 = b1.z, bs1 = b1.w;

            const float mv[TM] = {a0.x, a0.y, a0.z, a0.w, a1.x, a1.y, a1.z, a1.w};
            u64 m2[TM];
            #pragma unroll
            for (int i = 0; i < TM; i++) m2[i] = pack2(mv[i], mv[i]);  // ALU pipe

            // interleave packed and scalar FMAs per row i
            #pragma unroll
            for (int i = 0; i < TM; i++) {
                fma2(acc2[i * 3 + 0], m2[i], n[0]);
                fma2(acc2[i * 3 + 1], m2[i], n[1]);
                fma2(acc2[i * 3 + 2], m2[i], n[2]);
                accS[i * 2 + 0] = __fmaf_rn(mv[i], bs0, accS[i * 2 + 0]);
                accS[i * 2 + 1] = __fmaf_rn(mv[i], bs1, accS[i * 2 + 1]);
            }
        }
    };

    // ---- main loop: tiles 0..126  (k = 0..1015, the Eigen kc=1016 panel) ----
    for (int kb = 0; kb < NKB - 1; kb++) {
        const int cur = kb & 1, nxt = cur ^ 1;

        ra = *reinterpret_cast<const float4*>(Aptr + (size_t)(kb + 1) * BK);
        rb = *reinterpret_cast<const float4*>(Wptr + (size_t)(kb + 1) * BK);

        compute_tile(cur);

        const float av[4] = {ra.x, ra.y, ra.z, ra.w};
        const float bv[4] = {rb.x, rb.y, rb.z, rb.w};
        #pragma unroll
        for (int j = 0; j < 4; j++) {
            As[nxt][innerCol + j][innerRow] = av[j];
            Bs[nxt][innerCol + j][innerRow] = bv[j];
        }
        __syncthreads();
    }

    // ---- Eigen fold at k=1016: sum <- chain  (bitwise == fadd(0, chain)) ----
    u64   sum2[TM * 3];
    float sumS[TM * 2];
    #pragma unroll
    for (int i = 0; i < TM * 3; i++) { sum2[i] = acc2[i]; acc2[i] = 0ull; }
    #pragma unroll
    for (int i = 0; i < TM * 2; i++) { sumS[i] = accS[i]; accS[i] = 0.0f; }

    // ---- tail tile 127 (k = 1016..1023) ----
    compute_tile((NKB - 1) & 1);

    // ---- epilogue: o = fadd(fadd(sum, tail), bias)  (scalar, exactly R7) ----
    #pragma unroll
    for (int i = 0; i < TM; i++) {
        const size_t row = (size_t)cRow * BM + threadRow + i;
        {   // cols colLo .. colLo+3  (pairs p=0,1)
            const int col = cCol * BN + colLo;
            float4 bv = *reinterpret_cast<const float4*>(&bias[col]);
            float s[4], t[4];
            memcpy(&s[0], &sum2[i * 3 + 0], 8);
            memcpy(&s[2], &sum2[i * 3 + 1], 8);
            memcpy(&t[0], &acc2[i * 3 + 0], 8);
            memcpy(&t[2], &acc2[i * 3 + 1], 8);
            float4 o;
            o.x = __fadd_rn(__fadd_rn(s[0], t[0]), bv.x);
            o.y = __fadd_rn(__fadd_rn(s[1], t[1]), bv.y);
            o.z = __fadd_rn(__fadd_rn(s[2], t[2]), bv.z);
            o.w = __fadd_rn(__fadd_rn(s[3], t[3]), bv.w);
            *reinterpret_cast<float4*>(&g_I[row * HDIM + col]) = o;
        }
        {   // cols colHi .. colHi+3  (pair p=2 + scalars)
            const int col = cCol * BN + colHi;
            float4 bv = *reinterpret_cast<const float4*>(&bias[col]);
            float s[2], t[2];
            memcpy(&s[0], &sum2[i * 3 + 2], 8);
            memcpy(&t[0], &acc2[i * 3 + 2], 8);
            float4 o;
            o.x = __fadd_rn(__fadd_rn(s[0], t[0]), bv.x);
            o.y = __fadd_rn(__fadd_rn(s[1], t[1]), bv.y);
            o.z = __fadd_rn(__fadd_rn(sumS[i * 2 + 0], accS[i * 2 + 0]), bv.z);
            o.w = __fadd_rn(__fadd_rn(sumS[i * 2 + 1], accS[i * 2 + 1]), bv.w);
            *reinterpret_cast<float4*>(&g_I[row * HDIM + col]) = o;
        }
    }

    // ---- release: this CTA's slice of batch cRow/4 is globally visible ----
    __threadfence();
    __syncthreads();
    if (tid == 0) atomicAdd(&g_ready[cRow >> 2], 1u);
}

// ---------------------------------------------------------------------------
// Flag reset — head of every captured sequence (replay-deterministic).
// ---------------------------------------------------------------------------
__global__ void zero_flags() {
    if (threadIdx.x < BDIM) g_ready[threadIdx.x] = 0u;
}

// ---------------------------------------------------------------------------
// LIF scan v3 (R16): concurrent with the GEMM, per-batch flag-gated.
// Arithmetic bitwise-identical to R7/R14.
// ---------------------------------------------------------------------------
constexpr int SCHUNK = 16;

__global__ __launch_bounds__(128) void lif_scan(
    float* __restrict__ spikes,      // [B,T,H]
    float* __restrict__ mem_final)   // [B,H]
{
    const int idx = blockIdx.x * 128 + threadIdx.x;   // over B*H
    const int b = idx / HDIM;
    const int h = idx % HDIM;

    // wait until batch b's GEMM output is complete (32 producer CTAs)
    if (threadIdx.x == 0) {
        while (atomicAdd(&g_ready[b], 0u) < 32u) __nanosleep(256);
    }
    __syncthreads();
    __threadfence();   // acquire: order g_I loads after the observed release

    const float* Ip = g_I + (size_t)b * TDIM * HDIM + h;
    float* Sp = spikes + (size_t)b * TDIM * HDIM + h;

    float mem = 0.0f;
    for (int tb = 0; tb < TDIM; tb += SCHUNK) {
        float v[SCHUNK];
        #pragma unroll
        for (int j = 0; j < SCHUNK; j++)
            v[j] = Ip[(size_t)(tb + j) * HDIM];          // independent LDGs

        #pragma unroll
        for (int j = 0; j < SCHUNK; j++) {
            mem = __fadd_rn(__fmul_rn(ALPHA, mem), v[j]);
            const bool fire = (mem >= 1.0f);
            Sp[(size_t)(tb + j) * HDIM] = fire ? 1.0f : 0.0f;
            mem = fire ? 0.0f : mem;
        }
    }
    mem_final[idx] = mem;
}

// ---------------------------------------------------------------------------
// Overlap resources (host/driver objects only — created at static init).
// ---------------------------------------------------------------------------
static cudaStream_t g_s1;
static cudaEvent_t  g_evFork, g_evJoin;
static struct StreamInit {
    StreamInit() {
        cudaStreamCreateWithFlags(&g_s1, cudaStreamNonBlocking);
        cudaEventCreateWithFlags(&g_evFork, cudaEventDisableTiming);
        cudaEventCreateWithFlags(&g_evJoin, cudaEventDisableTiming);
    }
} g_streamInit;

extern "C" void kernel_launch(void* const* d_in, const int* in_sizes, int n_in,
                              void* d_out, int out_size)
{
    const float* x  = (const float*)d_in[0];   // [B,T,IN]
    const float* W  = (const float*)d_in[1];   // [HID,IN]
    const float* b  = (const float*)d_in[2];   // [HID]

    float* out      = (float*)d_out;
    float* spikes   = out;                                   // B*T*H floats
    float* mem_fin  = out + (size_t)MTOT * HDIM;             // B*H floats

    // 1) reset per-batch flags (main stream), fork point for the scan stream
    zero_flags<<<1, 64>>>();
    cudaEventRecord(g_evFork, 0);

    // 2) full GEMM (single kernel, 14 clean waves) on the main stream
    sgemm_nt_bias_eigen_f32x2<<<dim3(HDIM / BN, MTOT / BM), 256>>>(x, W, b);

    // 3) scan runs CONCURRENTLY on the side stream, gated per-batch by flags
    cudaStreamWaitEvent(g_s1, g_evFork, 0);
    lif_scan<<<(BDIM * HDIM) / 128, 128, 0, g_s1>>>(spikes, mem_fin);
    cudaEventRecord(g_evJoin, g_s1);

    // 4) join the side stream back into the main stream
    cudaStreamWaitEvent(0, g_evJoin, 0);
}